// round 13
// baseline (speedup 1.0000x reference)
#include <cuda_runtime.h>
#include <cstdint>

// instant-ngp HashEncoder forward: D=3, L=16, C=2, base=16, scale=2, 2^19 hashmap.
// R12: 16 threads/point (1 level each) + 32B-block corner-pair merge.
// Key identity: i0^i1 = ix^(ix+1) (hash term cancels; dense strides are
// multiples of 16). When ix mod 4 != 3 (75%), both x-corners of every corner
// pair live in one aligned 32B block -> ONE LDG.256 instead of two loads.
// Avg loads/point-level: 6 -> 5 (-17% gather wavefronts).

#define PRIME_Y 2654435761u
#define PRIME_Z 805459861u
#define HASH_MASK 524287u  // 2^19 - 1

__device__ __forceinline__ void stg_cs_f2(float* p, float2 v) {
    asm volatile("st.global.cs.v2.f32 [%0], {%1,%2};"
                 :: "l"(p), "f"(v.x), "f"(v.y) : "memory");
}

// 256-bit gather: 4 consecutive float2 table entries in one wavefront
__device__ __forceinline__ void ldg_256(const float* p, float2 E[4]) {
    uint32_t r0, r1, r2, r3, r4, r5, r6, r7;
    asm volatile("ld.global.nc.v8.b32 {%0,%1,%2,%3,%4,%5,%6,%7}, [%8];"
                 : "=r"(r0), "=r"(r1), "=r"(r2), "=r"(r3),
                   "=r"(r4), "=r"(r5), "=r"(r6), "=r"(r7)
                 : "l"(p));
    E[0] = make_float2(__uint_as_float(r0), __uint_as_float(r1));
    E[1] = make_float2(__uint_as_float(r2), __uint_as_float(r3));
    E[2] = make_float2(__uint_as_float(r4), __uint_as_float(r5));
    E[3] = make_float2(__uint_as_float(r6), __uint_as_float(r7));
}

// branchless 1-of-4 float2 select (constant-indexed regs + SELs, no spills)
__device__ __forceinline__ float2 sel4(const float2 E[4], uint32_t e) {
    const bool b0 = (e & 1u), b1 = (e & 2u);
    float ax = b0 ? E[1].x : E[0].x;
    float ay = b0 ? E[1].y : E[0].y;
    float bx = b0 ? E[3].x : E[2].x;
    float by = b0 ? E[3].y : E[2].y;
    return make_float2(b1 ? bx : ax, b1 ? by : ay);
}

__global__ __launch_bounds__(256) void hashenc_fwd(
    const float* __restrict__ inp,   // [B, 3]
    const float* __restrict__ emb,   // [TOTAL_PARAMS * 2] scalar float view
    float* __restrict__ out,         // [B, 32]
    int B)
{
    const int gtid = blockIdx.x * blockDim.x + threadIdx.x;
    const int p = gtid >> 4;       // point index
    const int l = gtid & 15;       // level index
    if (p >= B) return;

    const float x = (__ldg(inp + 3 * p + 0) + 1.0f) * 0.5f;
    const float y = (__ldg(inp + 3 * p + 1) + 1.0f) * 0.5f;
    const float z = (__ldg(inp + 3 * p + 2) + 1.0f) * 0.5f;

    const uint32_t res = 16u << l;
    const float scale = (float)res - 1.0f;
    const bool dense = (l < 3);

    uint32_t off;
    if (dense) off = (l == 0) ? 0u : (l == 1) ? 4096u : 36864u;
    else       off = 299008u + (uint32_t)(l - 3) * 524288u;

    const float px = x * scale + 0.5f;
    const float py = y * scale + 0.5f;
    const float pz = z * scale + 0.5f;

    const float gx = floorf(px);
    const float gy = floorf(py);
    const float gz = floorf(pz);

    const float tx = px - gx;
    const float ty = py - gy;
    const float tz = pz - gz;

    const uint32_t ix = (uint32_t)gx;
    const uint32_t iy = (uint32_t)gy;
    const uint32_t iz = (uint32_t)gz;

    const uint32_t dy = dense ? res       : PRIME_Y;
    const uint32_t dz = dense ? res * res : PRIME_Z;
    const uint32_t cy0 = iy * dy, cy1 = cy0 + dy;
    const uint32_t cz0 = iz * dz, cz1 = cz0 + dz;

    const float wy[2] = {1.0f - ty, ty};
    const float wz[2] = {1.0f - tz, tz};

    const float* lvl = emb + 2u * off;

    float sx = 0.0f, sy = 0.0f;

    // spread between the two x-corner indices; identical for all 4 corner
    // pairs (hash term cancels: i0^i1 = ix^(ix+1); dense strides are even)
    const uint32_t xorlow = ix ^ (ix + 1u);

    if (xorlow < 4u) {
        // 75%: both x-corners inside one aligned 32B block of 4 entries
#pragma unroll
        for (int c = 0; c < 4; ++c) {
            const uint32_t my = (c & 1) ? cy1 : cy0;
            const uint32_t mz = (c & 2) ? cz1 : cz0;
            const uint32_t i0 = dense ? (ix + my + mz)
                                      : ((ix ^ my ^ mz) & HASH_MASK);
            const uint32_t base = i0 & ~3u;
            const uint32_t e0 = i0 & 3u;
            const uint32_t e1 = e0 ^ xorlow;

            float2 E[4];
            ldg_256(lvl + 2u * base, E);
            const float2 g0 = sel4(E, e0);
            const float2 g1 = sel4(E, e1);

            const float wyz = wy[c & 1] * wz[(c >> 1) & 1];
            const float w1 = tx * wyz;
            const float w0 = wyz - w1;
            sx = fmaf(w0, g0.x, fmaf(w1, g1.x, sx));
            sy = fmaf(w0, g0.y, fmaf(w1, g1.y, sy));
        }
    } else {
        // 25% (ix mod 4 == 3): corners span >= 2 blocks, two loads each
        const uint32_t ix1 = ix + 1u;
#pragma unroll
        for (int c = 0; c < 4; ++c) {
            const uint32_t my = (c & 1) ? cy1 : cy0;
            const uint32_t mz = (c & 2) ? cz1 : cz0;
            uint32_t i0, i1;
            if (dense) {
                i0 = ix + my + mz;
                i1 = i0 + 1u;
            } else {
                const uint32_t m = my ^ mz;
                i0 = (ix  ^ m) & HASH_MASK;
                i1 = (ix1 ^ m) & HASH_MASK;
            }
            const float2 g0 = __ldg((const float2*)(lvl + 2u * i0));
            const float2 g1 = __ldg((const float2*)(lvl + 2u * i1));

            const float wyz = wy[c & 1] * wz[(c >> 1) & 1];
            const float w1 = tx * wyz;
            const float w0 = wyz - w1;
            sx = fmaf(w0, g0.x, fmaf(w1, g1.x, sx));
            sy = fmaf(w0, g0.y, fmaf(w1, g1.y, sy));
        }
    }

    // fully-coalesced 8B store: warp covers 2 points x 128B
    stg_cs_f2((float*)out + (size_t)gtid * 2, make_float2(sx, sy));
}

extern "C" void kernel_launch(void* const* d_in, const int* in_sizes, int n_in,
                              void* d_out, int out_size)
{
    const float* p0 = (const float*)d_in[0];
    const float* p1 = (const float*)d_in[1];
    const float* inp;
    const float* emb;
    int B;
    if (in_sizes[0] < in_sizes[1]) {
        inp = p0; emb = p1; B = in_sizes[0] / 3;
    } else {
        inp = p1; emb = p0; B = in_sizes[1] / 3;
    }
    const int threads = 256;
    const long long total = (long long)B * 16;
    const int blocks = (int)((total + threads - 1) / threads);
    hashenc_fwd<<<blocks, threads>>>(inp, emb, (float*)d_out, B);
}